// round 16
// baseline (speedup 1.0000x reference)
#include <cuda_runtime.h>
#include <cstdint>

// CrossAttention with seqlen-1 K/V broadcast:
//   out[b,t,:] = (visual_features[b] @ Wv + bv) @ Wp + bp   for every t.
// Softmax over T identical logits is exactly uniform; averaging T identical
// value rows returns the row. x/Wq/Wk are mathematically irrelevant.
//
// 3 graph nodes chained with PDL (launch overhead overlapped):
//   1) gemm1: g_part[sp] = partial(vf @ Wv)                grid 128 x 256
//   2) gemm2: z reduce (+bv) + partial(z @ Wp); the LAST
//      16 blocks (monotonic ticket) fold the 128 partials
//      + bp into g_w in-kernel (replaces wred)             grid 128 x 256
//   3) bcast: out[b,t,:] = g_w[b,:]                        grid 512 x 256

#define CC 1024
#define BB 4
#define TT_TOTAL 1024
#define SP 128
#define KCH (CC / SP)        // 8 K-rows per split block

__device__ float g_part [SP][BB * CC];   // partials of vf@Wv  (2 MB)
__device__ float g_part2[SP][BB * CC];   // partials of z@Wp   (2 MB)
__device__ float g_w[BB * CC];           // final w = z@Wp + bp
__device__ unsigned g_ctr;               // monotonic ticket (never reset)

// ---------------------------------------------------------------------------
// Kernel 1: g_part[sp][b*CC + j] = sum_{i in chunk} vf[b][i] * Wv[i][j]
__global__ void __launch_bounds__(256)
gemm1_kernel(const float* __restrict__ vf,   // [BB][CC]
             const float* __restrict__ W)    // Wv [CC][CC]
{
    __shared__ float s_in[BB][KCH];
    const int tid = threadIdx.x;
    const int sp  = blockIdx.x;
    const int k0  = sp * KCH;
    const int j0  = tid * 4;

    if (tid < BB * KCH) {                    // 32 values
        int b = tid >> 3, i = tid & 7;
        s_in[b][i] = vf[b * CC + k0 + i];
    }
    __syncthreads();

    float4 acc[BB] = {};
    const float4* __restrict__ Wc =
        reinterpret_cast<const float4*>(W + (size_t)k0 * CC + j0);
    #pragma unroll
    for (int i = 0; i < KCH; i++) {
        float4 w = Wc[(size_t)i * (CC / 4)];
        #pragma unroll
        for (int b = 0; b < BB; b++) {
            float s = s_in[b][i];
            acc[b].x += s * w.x; acc[b].y += s * w.y;
            acc[b].z += s * w.z; acc[b].w += s * w.w;
        }
    }
    #pragma unroll
    for (int b = 0; b < BB; b++)
        *reinterpret_cast<float4*>(&g_part[sp][b * CC + j0]) = acc[b];
}

// ---------------------------------------------------------------------------
// Kernel 2: z-slice reduce (+bv), partial(z @ Wp), then ticketed tail reduce.
__global__ void __launch_bounds__(256)
gemm2_kernel(const float* __restrict__ bv,
             const float* __restrict__ W,    // Wp [CC][CC]
             const float* __restrict__ bp)
{
    __shared__ float s_red[8][32];
    __shared__ float s_z[BB][KCH];
    __shared__ unsigned s_ticket;
    const int tid = threadIdx.x;
    const int sp  = blockIdx.x;
    const int k0  = sp * KCH;
    const int j0  = tid * 4;

    cudaGridDependencySynchronize();         // PDL: wait for gemm1 writes

    // Reduce z slice: 32 (b,i) pairs x 128 partials (8 groups x 16 sp each).
    {
        const int p = tid & 31, g = tid >> 5;
        const int b = p >> 3,  i = p & 7;
        float s = 0.f;
        #pragma unroll
        for (int u = 0; u < 16; u++)
            s += g_part[g * 16 + u][b * CC + k0 + i];
        s_red[g][p] = s;
    }
    __syncthreads();
    if (tid < 32) {
        int b = tid >> 3, i = tid & 7;
        float z = bv[k0 + i];
        #pragma unroll
        for (int g = 0; g < 8; g++) z += s_red[g][tid];
        s_z[b][i] = z;
    }
    __syncthreads();

    float4 acc[BB] = {};
    const float4* __restrict__ Wc =
        reinterpret_cast<const float4*>(W + (size_t)k0 * CC + j0);
    #pragma unroll
    for (int i = 0; i < KCH; i++) {
        float4 w = Wc[(size_t)i * (CC / 4)];
        #pragma unroll
        for (int b = 0; b < BB; b++) {
            float s = s_z[b][i];
            acc[b].x += s * w.x; acc[b].y += s * w.y;
            acc[b].z += s * w.z; acc[b].w += s * w.w;
        }
    }
    #pragma unroll
    for (int b = 0; b < BB; b++)
        *reinterpret_cast<float4*>(&g_part2[sp][b * CC + j0]) = acc[b];

    // ---- ticketed tail: last 16 blocks fold partials (+bp) into g_w ----
    __threadfence();                         // release this block's partials
    if (tid == 0) s_ticket = atomicAdd(&g_ctr, 1u);
    __syncthreads();
    const unsigned old  = s_ticket;
    const unsigned slot = old % SP;          // position within this launch
    if (slot >= SP - 16) {
        const unsigned target = (old / SP + 1u) * SP;
        if (tid == 0)
            while (*(volatile unsigned*)&g_ctr < target) { }
        __syncthreads();
        __threadfence();                     // acquire other blocks' partials

        const int e = (int)(slot - (SP - 16)) * 256 + tid;   // 0..4095
        float s = bp[e & (CC - 1)];
        #pragma unroll 16
        for (int p = 0; p < SP; p++)
            s += g_part2[p][e];
        g_w[e] = s;
    }
}

// ---------------------------------------------------------------------------
// Kernel 3: broadcast. 512 blocks x 256 thr: 1 LDG.128 + 8 STG.128 each.
#define ROWS_PER_BLK 8
__global__ void __launch_bounds__(256)
bcast_kernel(float* __restrict__ out)        // [BB][T][CC]
{
    cudaGridDependencySynchronize();         // PDL: wait for g_w

    const int b  = blockIdx.x >> 7;
    const int t0 = (blockIdx.x & 127) * ROWS_PER_BLK;

    const float4 wv = *(reinterpret_cast<const float4*>(&g_w[b * CC]) + threadIdx.x);

    float4* o = reinterpret_cast<float4*>(out + (size_t)(b * TT_TOTAL + t0) * CC)
                + threadIdx.x;
    #pragma unroll
    for (int t = 0; t < ROWS_PER_BLK; t++)
        o[(size_t)t * (CC / 4)] = wv;
}

extern "C" void kernel_launch(void* const* d_in, const int* in_sizes, int n_in,
                              void* d_out, int out_size)
{
    // metadata order: x, visual_features, Wq, bq, Wk, bk, Wv, bv, Wp, bp
    const float* vf = (const float*)d_in[1];
    const float* Wv = (const float*)d_in[6];
    const float* bv = (const float*)d_in[7];
    const float* Wp = (const float*)d_in[8];
    const float* bp = (const float*)d_in[9];
    float* out = (float*)d_out;

    gemm1_kernel<<<SP, 256>>>(vf, Wv);

    cudaLaunchAttribute pdl[1];
    pdl[0].id = cudaLaunchAttributeProgrammaticStreamSerialization;
    pdl[0].val.programmaticStreamSerializationAllowed = 1;

    {   // gemm2 with PDL edge from gemm1
        cudaLaunchConfig_t cfg = {};
        cfg.gridDim  = dim3(SP);
        cfg.blockDim = dim3(256);
        cfg.stream   = 0;
        cfg.attrs    = pdl;
        cfg.numAttrs = 1;
        cudaLaunchKernelEx(&cfg, gemm2_kernel, bv, Wp, bp);
    }
    {   // bcast with PDL edge from gemm2
        cudaLaunchConfig_t cfg = {};
        cfg.gridDim  = dim3(BB * (TT_TOTAL / ROWS_PER_BLK));
        cfg.blockDim = dim3(256);
        cfg.stream   = 0;
        cfg.attrs    = pdl;
        cfg.numAttrs = 1;
        cudaLaunchKernelEx(&cfg, bcast_kernel, out);
    }
}

// round 17
// speedup vs baseline: 1.3200x; 1.3200x over previous
#include <cuda_runtime.h>
#include <cstdint>

// CrossAttention with seqlen-1 K/V broadcast:
//   out[b,t,:] = (visual_features[b] @ Wv + bv) @ Wp + bp   for every t.
// Softmax over T identical logits is exactly uniform; averaging T identical
// value rows returns the row. x/Wq/Wk are mathematically irrelevant.
//
// R15's best 4-node pipeline + PDL edges only (single-variable experiment):
//   1) gemm1: g_part[sp] = partial(vf @ Wv)       grid 128 x 256
//   2) gemm2: z reduce (+bv) + partial(z @ Wp)    grid 128 x 256   [PDL]
//   3) wred:  g_w = bp + sum of 128 partials      grid 128 x 256   [PDL]
//   4) bcast: out[b,t,:] = g_w[b,:]               grid 512 x 256   [PDL]

#define CC 1024
#define BB 4
#define TT_TOTAL 1024
#define SP 128
#define KCH (CC / SP)        // 8 K-rows per split block

__device__ float g_part [SP][BB * CC];   // partials of vf@Wv  (2 MB)
__device__ float g_part2[SP][BB * CC];   // partials of z@Wp   (2 MB)
__device__ float g_w[BB * CC];           // final w = z@Wp + bp

// ---------------------------------------------------------------------------
// Kernel 1: g_part[sp][b*CC + j] = sum_{i in chunk} vf[b][i] * Wv[i][j]
__global__ void __launch_bounds__(256)
gemm1_kernel(const float* __restrict__ vf,   // [BB][CC]
             const float* __restrict__ W)    // Wv [CC][CC]
{
    __shared__ float s_in[BB][KCH];
    const int tid = threadIdx.x;
    const int sp  = blockIdx.x;
    const int k0  = sp * KCH;
    const int j0  = tid * 4;

    if (tid < BB * KCH) {                    // 32 values
        int b = tid >> 3, i = tid & 7;
        s_in[b][i] = vf[b * CC + k0 + i];
    }
    __syncthreads();

    float4 acc[BB] = {};
    const float4* __restrict__ Wc =
        reinterpret_cast<const float4*>(W + (size_t)k0 * CC + j0);
    #pragma unroll
    for (int i = 0; i < KCH; i++) {
        float4 w = Wc[(size_t)i * (CC / 4)];
        #pragma unroll
        for (int b = 0; b < BB; b++) {
            float s = s_in[b][i];
            acc[b].x += s * w.x; acc[b].y += s * w.y;
            acc[b].z += s * w.z; acc[b].w += s * w.w;
        }
    }
    #pragma unroll
    for (int b = 0; b < BB; b++)
        *reinterpret_cast<float4*>(&g_part[sp][b * CC + j0]) = acc[b];
}

// ---------------------------------------------------------------------------
// Kernel 2: z-slice reduce (+bv) prologue, then partial(z @ Wp).
__global__ void __launch_bounds__(256)
gemm2_kernel(const float* __restrict__ bv,
             const float* __restrict__ W)    // Wp [CC][CC]
{
    __shared__ float s_red[8][32];
    __shared__ float s_z[BB][KCH];
    const int tid = threadIdx.x;
    const int sp  = blockIdx.x;
    const int k0  = sp * KCH;
    const int j0  = tid * 4;

    cudaGridDependencySynchronize();         // PDL: gemm1 complete

    // Reduce z slice: 32 (b,i) pairs x 128 partials (8 groups x 16 sp each).
    {
        const int p = tid & 31, g = tid >> 5;
        const int b = p >> 3,  i = p & 7;
        float s = 0.f;
        #pragma unroll
        for (int u = 0; u < 16; u++)
            s += g_part[g * 16 + u][b * CC + k0 + i];
        s_red[g][p] = s;
    }
    __syncthreads();
    if (tid < 32) {
        int b = tid >> 3, i = tid & 7;
        float z = bv[k0 + i];
        #pragma unroll
        for (int g = 0; g < 8; g++) z += s_red[g][tid];
        s_z[b][i] = z;
    }
    __syncthreads();

    float4 acc[BB] = {};
    const float4* __restrict__ Wc =
        reinterpret_cast<const float4*>(W + (size_t)k0 * CC + j0);
    #pragma unroll
    for (int i = 0; i < KCH; i++) {
        float4 w = Wc[(size_t)i * (CC / 4)];
        #pragma unroll
        for (int b = 0; b < BB; b++) {
            float s = s_z[b][i];
            acc[b].x += s * w.x; acc[b].y += s * w.y;
            acc[b].z += s * w.z; acc[b].w += s * w.w;
        }
    }
    #pragma unroll
    for (int b = 0; b < BB; b++)
        *reinterpret_cast<float4*>(&g_part2[sp][b * CC + j0]) = acc[b];
}

// ---------------------------------------------------------------------------
// Kernel 3: g_w[e] = bp[e & 1023] + sum_{sp<128} g_part2[sp][e]
// 128 blocks x 256 thr; block covers 32 elements, 8 sp-groups of 16.
__global__ void __launch_bounds__(256)
wred_kernel(const float* __restrict__ bp)
{
    __shared__ float s[8][32];

    cudaGridDependencySynchronize();         // PDL: gemm2 complete

    const int e0 = blockIdx.x * 32;
    const int e  = threadIdx.x & 31, g = threadIdx.x >> 5;

    float r = 0.f;
    #pragma unroll
    for (int u = 0; u < 16; u++)
        r += g_part2[g * 16 + u][e0 + e];
    s[g][e] = r;
    __syncthreads();
    if (threadIdx.x < 32) {
        float w = bp[(e0 + threadIdx.x) & (CC - 1)];
        #pragma unroll
        for (int g2 = 0; g2 < 8; g2++) w += s[g2][threadIdx.x];
        g_w[e0 + threadIdx.x] = w;
    }
}

// ---------------------------------------------------------------------------
// Kernel 4: broadcast. 512 blocks x 256 thr: 1 LDG.128 + 8 STG.128 each.
#define ROWS_PER_BLK 8
__global__ void __launch_bounds__(256)
bcast_kernel(float* __restrict__ out)        // [BB][T][CC]
{
    cudaGridDependencySynchronize();         // PDL: wred complete

    const int b  = blockIdx.x >> 7;
    const int t0 = (blockIdx.x & 127) * ROWS_PER_BLK;

    const float4 wv = *(reinterpret_cast<const float4*>(&g_w[b * CC]) + threadIdx.x);

    float4* o = reinterpret_cast<float4*>(out + (size_t)(b * TT_TOTAL + t0) * CC)
                + threadIdx.x;
    #pragma unroll
    for (int t = 0; t < ROWS_PER_BLK; t++)
        o[(size_t)t * (CC / 4)] = wv;
}

extern "C" void kernel_launch(void* const* d_in, const int* in_sizes, int n_in,
                              void* d_out, int out_size)
{
    // metadata order: x, visual_features, Wq, bq, Wk, bk, Wv, bv, Wp, bp
    const float* vf = (const float*)d_in[1];
    const float* Wv = (const float*)d_in[6];
    const float* bv = (const float*)d_in[7];
    const float* Wp = (const float*)d_in[8];
    const float* bp = (const float*)d_in[9];
    float* out = (float*)d_out;

    gemm1_kernel<<<SP, 256>>>(vf, Wv);

    cudaLaunchAttribute pdl[1];
    pdl[0].id = cudaLaunchAttributeProgrammaticStreamSerialization;
    pdl[0].val.programmaticStreamSerializationAllowed = 1;

    {
        cudaLaunchConfig_t cfg = {};
        cfg.gridDim  = dim3(SP);
        cfg.blockDim = dim3(256);
        cfg.stream   = 0;
        cfg.attrs    = pdl;
        cfg.numAttrs = 1;
        cudaLaunchKernelEx(&cfg, gemm2_kernel, bv, Wp);
    }
    {
        cudaLaunchConfig_t cfg = {};
        cfg.gridDim  = dim3((BB * CC) / 32);
        cfg.blockDim = dim3(256);
        cfg.stream   = 0;
        cfg.attrs    = pdl;
        cfg.numAttrs = 1;
        cudaLaunchKernelEx(&cfg, wred_kernel, bp);
    }
    {
        cudaLaunchConfig_t cfg = {};
        cfg.gridDim  = dim3(BB * (TT_TOTAL / ROWS_PER_BLK));
        cfg.blockDim = dim3(256);
        cfg.stream   = 0;
        cfg.attrs    = pdl;
        cfg.numAttrs = 1;
        cudaLaunchKernelEx(&cfg, bcast_kernel, out);
    }
}